// round 12
// baseline (speedup 1.0000x reference)
#include <cuda_runtime.h>
#include <math.h>

#define BB 4
#define NN 3000
#define CC 21
#define BN (BB*NN)

#define NGROUPS (BB*(CC-1))            // 80
#define THREADS 512
#define PREP_BLOCKS ((BN + THREADS - 1) / THREADS)   // 24
#define NBLK (NGROUPS + PREP_BLOCKS)   // 104
#define MAXM  320
#define WMAX  10
#define FCAP  448

// out layout (float32): [rounded BN*4][sigmoid BN][boxes BN*4][probs BN*C][keep BN]

// nmsbuf (36864 B) overlays (NMS phase only):
//   fast:     maskb u32 [0,12800) | tlbr f4 [12800,17920) | area f [17920,19200)
//             sidx i32 [19200,20480) | keptw u32 [20480,20520)
//   fallback: keys u64 [0,32768) | st u8 [32768,35840)
__shared__ unsigned char      nmsbuf[36864];
__shared__ unsigned long long keysbuf[MAXM];
__shared__ int                candbuf[FCAP];
__shared__ int s_count, s_filt;

__device__ __forceinline__ void load_box(const float* __restrict__ nms_reg,
                                         const float* __restrict__ rcnn_reg,
                                         float red, int gidx, float4* box)
{
    float4 r  = ((const float4*)nms_reg)[gidx];
    float4 rg = ((const float4*)rcnn_reg)[gidx];
    float q0 = __fdiv_rn(floorf(__fmul_rn(r.x, red)), red);
    float q1 = __fdiv_rn(floorf(__fmul_rn(r.y, red)), red);
    float q2 = __fdiv_rn(ceilf(__fmul_rn(r.z, red)), red);
    float q3 = __fdiv_rn(ceilf(__fmul_rn(r.w, red)), red);
    box->x = __fadd_rn(rg.x, q0);
    box->y = __fadd_rn(rg.y, q1);
    box->z = __fadd_rn(rg.z, q2);
    box->w = __fadd_rn(rg.w, q3);
}

__global__ void __launch_bounds__(THREADS)
fused_kernel(const float* __restrict__ nms_reg,
             const float* __restrict__ nms_cls,
             const float* __restrict__ rcnn_reg,
             const float* __restrict__ rcnn_cls,
             const unsigned int* __restrict__ red_raw,
             float* __restrict__ out)
{
    int tid  = threadIdx.x;
    int lane = tid & 31;
    int bid  = blockIdx.x;

    unsigned int wr = red_raw[0];
    float red = (wr < 0x10000u) ? (float)wr : __uint_as_float(wr);

    float* o_keep = out + BN * 9 + BN * CC;

    if (bid >= NGROUPS) {
        // ======================= prep path (R6-style direct) ================
        int idx = (bid - NGROUPS) * THREADS + tid;
        if (idx >= BN) return;

        float* o_round = out;
        float* o_sig   = out + BN * 4;
        float* o_boxes = out + BN * 5;
        float* o_probs = out + BN * 9;

        float4 r = ((const float4*)nms_reg)[idx];
        float q0 = __fdiv_rn(floorf(__fmul_rn(r.x, red)), red);
        float q1 = __fdiv_rn(floorf(__fmul_rn(r.y, red)), red);
        float q2 = __fdiv_rn(ceilf(__fmul_rn(r.z, red)), red);
        float q3 = __fdiv_rn(ceilf(__fmul_rn(r.w, red)), red);
        ((float4*)o_round)[idx] = make_float4(q0, q1, q2, q3);

        float4 rg = ((const float4*)rcnn_reg)[idx];
        ((float4*)o_boxes)[idx] = make_float4(
            __fadd_rn(rg.x, q0), __fadd_rn(rg.y, q1),
            __fadd_rn(rg.z, q2), __fadd_rn(rg.w, q3));

        float s = nms_cls[idx];
        o_sig[idx] = 1.0f / (1.0f + expf(-s));

        float l[CC];
        float m = -INFINITY;
        #pragma unroll
        for (int c = 0; c < CC; c++) {
            l[c] = rcnn_cls[(size_t)idx * CC + c];
            m = fmaxf(m, l[c]);
        }
        float p[CC];
        float sum = 0.0f;
        #pragma unroll
        for (int c = 0; c < CC; c++) {
            p[c] = expf(l[c] - m);
            sum += p[c];
        }
        float inv = __fdiv_rn(1.0f, sum);
        int   am   = 0;
        float best = -INFINITY;
        #pragma unroll
        for (int c = 0; c < CC; c++) {
            p[c] = __fmul_rn(p[c], inv);
            o_probs[(size_t)idx * CC + c] = p[c];
            if (p[c] > best) { best = p[c]; am = c; }
        }
        // prep owns keep for amax==0 boxes (reference never keeps them)
        if (am == 0) o_keep[idx] = 0.0f;
        return;
    }

    // ======================= group path =======================
    int b   = bid / (CC - 1);
    int cls = 1 + bid % (CC - 1);

    if (tid == 0) { s_count = 0; s_filt = 0; }
    __syncthreads();

    // --- pass 1: cheap superset filter (tree max + threshold), compact ---
    for (int n = tid; n < NN; n += THREADS) {
        const float* lg = rcnn_cls + ((size_t)b * NN + n) * CC;
        float l[CC];
        #pragma unroll
        for (int c = 0; c < CC; c++) l[c] = lg[c];
        // depth-5 max tree (fmaxf is associative-safe)
        float m[CC];
        #pragma unroll
        for (int c = 0; c < CC; c++) m[c] = l[c];
        #pragma unroll
        for (int s = 1; s < CC; s <<= 1) {
            #pragma unroll
            for (int c = 0; c + s < CC; c += 2 * s)
                m[c] = fmaxf(m[c], m[c + s]);
        }
        if (l[cls] >= m[0] - 1e-5f) {
            int pos = atomicAdd(&s_filt, 1);
            if (pos < FCAP) candbuf[pos] = n;
        }
    }
    __syncthreads();
    int F = s_filt;

    if (F <= FCAP) {
        // --- pass 2: exact reference-sequence candidacy + score (dense) ---
        for (int q = tid; q < F; q += THREADS) {
            int n = candbuf[q];
            const float* lg = rcnn_cls + ((size_t)b * NN + n) * CC;
            float l[CC];
            float bestl = -INFINITY, second = -INFINITY;
            int am = 0;
            #pragma unroll
            for (int c = 0; c < CC; c++) {
                float v = lg[c];
                l[c] = v;
                if (v > bestl) { second = bestl; bestl = v; am = c; }
                else if (v > second) second = v;
            }
            bool cand;
            float score = 0.0f;
            if (bestl - second > 1e-5f) {
                cand = (am == cls);
                if (cand) {
                    float sum = 0.0f;
                    #pragma unroll
                    for (int c = 0; c < CC; c++) sum += expf(l[c] - bestl);
                    float inv = __fdiv_rn(1.0f, sum);
                    score = __fmul_rn(expf(l[cls] - bestl), inv);
                }
            } else {
                float sum = 0.0f;
                #pragma unroll
                for (int c = 0; c < CC; c++) sum += expf(l[c] - bestl);
                float inv = __fdiv_rn(1.0f, sum);
                int amp = 0; float bp = -INFINITY; float sc = 0.0f;
                #pragma unroll
                for (int c = 0; c < CC; c++) {
                    float p = __fmul_rn(expf(l[c] - bestl), inv);
                    if (p > bp) { bp = p; amp = c; }
                    if (c == cls) sc = p;
                }
                cand = (amp == cls);
                score = sc;
            }
            if (cand) {
                int pos = atomicAdd(&s_count, 1);
                if (pos < MAXM) {
                    unsigned int sb = __float_as_uint(score);
                    keysbuf[pos] = ((unsigned long long)sb << 32)
                                 | (unsigned long long)(0xFFFFFFFFu - (unsigned)n);
                }
            }
        }
    }
    __syncthreads();

    int M = (F <= FCAP) ? s_count : (MAXM + 1);   // overflow -> fallback
    if (M == 0) return;

    if (M <= MAXM) {
        unsigned int* maskb = (unsigned int*)nmsbuf;
        float4*       tlbr  = (float4*)(nmsbuf + 12800);
        float*        area  = (float*)(nmsbuf + 17920);
        int*          sidx  = (int*)(nmsbuf + 19200);
        unsigned int* keptw = (unsigned int*)(nmsbuf + 20480);
        const int W = (M + 31) >> 5;

        // rank sort (keys unique -> deterministic descending order)
        unsigned long long myk; int myrank = -1;
        if (tid < M) {
            myk = keysbuf[tid];
            int r = 0;
            for (int j = 0; j < M; j++) r += (keysbuf[j] > myk);
            myrank = r;
        }
        __syncthreads();
        if (myrank >= 0) keysbuf[myrank] = myk;
        __syncthreads();

        // stage sorted boxes (bit-exact recompute) + areas + indices
        if (tid < M) {
            int n = (int)(0xFFFFFFFFu - (unsigned)(keysbuf[tid] & 0xFFFFFFFFu));
            sidx[tid] = n;
            float4 v;
            load_box(nms_reg, rcnn_reg, red, b * NN + n, &v);
            tlbr[tid] = v;
            area[tid] = __fmul_rn(fmaxf(__fsub_rn(v.z, v.x), 0.0f),
                                  fmaxf(__fsub_rn(v.w, v.y), 0.0f));
        }
        __syncthreads();

        // suppression matrix: thread owns (row i, word w); no atomics
        int ncells = M * W;
        for (int t = tid; t < ncells; t += THREADS) {
            int i = t / W;
            int w = t - i * W;
            int jbase = w << 5;
            unsigned int word = 0;
            if (jbase + 31 > i) {
                float4 bi = tlbr[i];
                float  ai = area[i];
                #pragma unroll 4
                for (int bit = 0; bit < 32; bit++) {
                    int j = jbase + bit;
                    if (j > i && j < M) {
                        float4 bj = tlbr[j];
                        float ih = fmaxf(__fsub_rn(fminf(bi.z, bj.z), fmaxf(bi.x, bj.x)), 0.0f);
                        float iw = fmaxf(__fsub_rn(fminf(bi.w, bj.w), fmaxf(bi.y, bj.y)), 0.0f);
                        float inter = __fmul_rn(ih, iw);
                        float uni   = __fsub_rn(__fadd_rn(ai, area[j]), inter);
                        float iou   = __fdiv_rn(inter, fmaxf(uni, 1e-9f));
                        if (iou > 0.5f) word |= (1u << bit);
                    }
                }
            }
            maskb[i * W + w] = word;
        }
        __syncthreads();

        // warp 0: branchless chunked greedy scan
        if (tid < 32) {
            unsigned int R = 0u, K = 0u;
            int ldslane = (lane < W) ? lane : (W - 1);
            unsigned int lanemask = (lane < W) ? 0xFFFFFFFFu : 0u;
            for (int c = 0; c < W; c++) {
                unsigned int curw = __shfl_sync(0xFFFFFFFFu, R, c);
                int ibase = c << 5;
                #pragma unroll 8
                for (int bit = 0; bit < 32; bit++) {
                    int i = ibase + bit;
                    unsigned int valid = (i < M) ? 0xFFFFFFFFu : 0u;
                    unsigned int keptm = (~(curw >> bit) & 1u) ? valid : 0u;
                    unsigned int mwc = maskb[i * W + c]       & valid;
                    unsigned int mwl = maskb[i * W + ldslane] & lanemask & valid;
                    curw |= (mwc & keptm);
                    R    |= (mwl & keptm);
                    K    |= ((lane == c) ? (keptm & (1u << bit)) : 0u);
                }
            }
            if (lane < W) keptw[lane] = K;
        }
        __syncthreads();

        // keep (0/1); in-batch index 0 never kept (reference scan quirk)
        if (tid < M) {
            int n = sidx[tid];
            bool kept = (keptw[tid >> 5] >> (tid & 31)) & 1u;
            o_keep[b * NN + n] = (kept && n != 0) ? 1.0f : 0.0f;
        }
    } else {
        // -------- fallback (overflow; statistically unreachable) --------
        unsigned long long* keys = (unsigned long long*)nmsbuf;   // cap 4096
        unsigned char*      st   = nmsbuf + 32768;                // cap 3000+
        if (tid == 0) s_count = 0;
        __syncthreads();
        // exact re-gather, direct reads
        for (int n = tid; n < NN; n += THREADS) {
            const float* lg = rcnn_cls + ((size_t)b * NN + n) * CC;
            float l[CC];
            float bestl = -INFINITY;
            #pragma unroll
            for (int c = 0; c < CC; c++) { l[c] = lg[c]; bestl = fmaxf(bestl, l[c]); }
            float sum = 0.0f;
            #pragma unroll
            for (int c = 0; c < CC; c++) sum += expf(l[c] - bestl);
            float inv = __fdiv_rn(1.0f, sum);
            int amp = 0; float bp = -INFINITY; float sc = 0.0f;
            #pragma unroll
            for (int c = 0; c < CC; c++) {
                float p = __fmul_rn(expf(l[c] - bestl), inv);
                if (p > bp) { bp = p; amp = c; }
                if (c == cls) sc = p;
            }
            if (amp == cls) {
                int pos = atomicAdd(&s_count, 1);
                unsigned int sb = __float_as_uint(sc);
                keys[pos] = ((unsigned long long)sb << 32)
                          | (unsigned long long)(0xFFFFFFFFu - (unsigned)n);
            }
        }
        __syncthreads();
        M = s_count;

        int P = 1;
        while (P < M) P <<= 1;
        for (int i = M + tid; i < P; i += THREADS) keys[i] = 0ULL;
        __syncthreads();
        for (int k = 2; k <= P; k <<= 1) {
            for (int j = k >> 1; j > 0; j >>= 1) {
                for (int i = tid; i < P; i += THREADS) {
                    int ixj = i ^ j;
                    if (ixj > i) {
                        unsigned long long a = keys[i];
                        unsigned long long c = keys[ixj];
                        bool dirDesc = ((i & k) == 0);
                        if ((a < c) == dirDesc) { keys[i] = c; keys[ixj] = a; }
                    }
                }
                __syncthreads();
            }
        }
        for (int i = tid; i < M; i += THREADS) st[i] = 0;   // 0=alive 1=supp 2=kept
        __syncthreads();
        for (int i = 0; i < M; i++) {
            if (st[i] == 0) {
                int ni = (int)(0xFFFFFFFFu - (unsigned)(keys[i] & 0xFFFFFFFFu));
                float4 vi; load_box(nms_reg, rcnn_reg, red, b * NN + ni, &vi);
                float ai = __fmul_rn(fmaxf(__fsub_rn(vi.z, vi.x), 0.0f),
                                     fmaxf(__fsub_rn(vi.w, vi.y), 0.0f));
                if (tid == 0) st[i] = 2;
                for (int j = i + 1 + tid; j < M; j += THREADS) {
                    if (st[j]) continue;
                    int nj = (int)(0xFFFFFFFFu - (unsigned)(keys[j] & 0xFFFFFFFFu));
                    float4 vj; load_box(nms_reg, rcnn_reg, red, b * NN + nj, &vj);
                    float aj = __fmul_rn(fmaxf(__fsub_rn(vj.z, vj.x), 0.0f),
                                         fmaxf(__fsub_rn(vj.w, vj.y), 0.0f));
                    float ih = fmaxf(__fsub_rn(fminf(vi.z, vj.z), fmaxf(vi.x, vj.x)), 0.0f);
                    float iw = fmaxf(__fsub_rn(fminf(vi.w, vj.w), fmaxf(vi.y, vj.y)), 0.0f);
                    float inter = __fmul_rn(ih, iw);
                    float uni   = __fsub_rn(__fadd_rn(ai, aj), inter);
                    float iou   = __fdiv_rn(inter, fmaxf(uni, 1e-9f));
                    if (iou > 0.5f) st[j] = 1;
                }
            }
            __syncthreads();
        }
        for (int i = tid; i < M; i += THREADS) {
            int n = (int)(0xFFFFFFFFu - (unsigned)(keys[i] & 0xFFFFFFFFu));
            o_keep[b * NN + n] = (st[i] == 2 && n != 0) ? 1.0f : 0.0f;
        }
    }
}

extern "C" void kernel_launch(void* const* d_in, const int* in_sizes, int n_in,
                              void* d_out, int out_size)
{
    const float* nms_reg  = (const float*)d_in[0];
    const float* nms_cls  = (const float*)d_in[1];
    const float* rcnn_reg = (const float*)d_in[2];
    const float* rcnn_cls = (const float*)d_in[3];
    const unsigned int* red = (const unsigned int*)d_in[4];
    float* out = (float*)d_out;

    fused_kernel<<<NBLK, THREADS>>>(nms_reg, nms_cls, rcnn_reg, rcnn_cls, red, out);
}

// round 13
// speedup vs baseline: 1.1601x; 1.1601x over previous
#include <cuda_runtime.h>
#include <math.h>

#define BB 4
#define NN 3000
#define CC 21
#define BN (BB*NN)

#define NGROUPS (BB*(CC-1))            // 80
#define THREADS 256
#define NSEG    8
#define SEGSZ   ((NN + NSEG - 1) / NSEG)   // 375
#define SEGCAP  384
#define GATHER_BLOCKS (NGROUPS * NSEG)     // 640
#define PREP_BLOCKS ((BN + THREADS - 1) / THREADS)   // 47
#define NBLK1 (GATHER_BLOCKS + PREP_BLOCKS)          // 687
#define MAXM  320
#define WMAX  10

// ---------------------------------------------------------------------------
// device scratch (no allocations allowed)
// ---------------------------------------------------------------------------
__device__ int                g_segcnt[GATHER_BLOCKS];
__device__ unsigned long long g_seglist[GATHER_BLOCKS * SEGCAP];

// out layout (float32): [rounded BN*4][sigmoid BN][boxes BN*4][probs BN*C][keep BN]

__device__ __forceinline__ void load_box(const float* __restrict__ nms_reg,
                                         const float* __restrict__ rcnn_reg,
                                         float red, int gidx, float4* box)
{
    float4 r  = ((const float4*)nms_reg)[gidx];
    float4 rg = ((const float4*)rcnn_reg)[gidx];
    float q0 = __fdiv_rn(floorf(__fmul_rn(r.x, red)), red);
    float q1 = __fdiv_rn(floorf(__fmul_rn(r.y, red)), red);
    float q2 = __fdiv_rn(ceilf(__fmul_rn(r.z, red)), red);
    float q3 = __fdiv_rn(ceilf(__fmul_rn(r.w, red)), red);
    box->x = __fadd_rn(rg.x, q0);
    box->y = __fadd_rn(rg.y, q1);
    box->z = __fadd_rn(rg.z, q2);
    box->w = __fadd_rn(rg.w, q3);
}

// ===========================================================================
// Kernel 1: prep (47 blocks) + segmented gather (640 blocks)
// ===========================================================================
__global__ void __launch_bounds__(THREADS)
k1_prep_gather(const float* __restrict__ nms_reg,
               const float* __restrict__ nms_cls,
               const float* __restrict__ rcnn_reg,
               const float* __restrict__ rcnn_cls,
               const unsigned int* __restrict__ red_raw,
               float* __restrict__ out)
{
    __shared__ int s_count;
    int tid = threadIdx.x;
    int bid = blockIdx.x;

    unsigned int wr = red_raw[0];
    float red = (wr < 0x10000u) ? (float)wr : __uint_as_float(wr);

    float* o_keep = out + BN * 9 + BN * CC;

    if (bid >= GATHER_BLOCKS) {
        // ------------------------- prep path (R6-verbatim) -----------------
        int idx = (bid - GATHER_BLOCKS) * THREADS + tid;
        if (idx >= BN) return;

        float* o_round = out;
        float* o_sig   = out + BN * 4;
        float* o_boxes = out + BN * 5;
        float* o_probs = out + BN * 9;

        float4 r = ((const float4*)nms_reg)[idx];
        float q0 = __fdiv_rn(floorf(__fmul_rn(r.x, red)), red);
        float q1 = __fdiv_rn(floorf(__fmul_rn(r.y, red)), red);
        float q2 = __fdiv_rn(ceilf(__fmul_rn(r.z, red)), red);
        float q3 = __fdiv_rn(ceilf(__fmul_rn(r.w, red)), red);
        ((float4*)o_round)[idx] = make_float4(q0, q1, q2, q3);

        float4 rg = ((const float4*)rcnn_reg)[idx];
        ((float4*)o_boxes)[idx] = make_float4(
            __fadd_rn(rg.x, q0), __fadd_rn(rg.y, q1),
            __fadd_rn(rg.z, q2), __fadd_rn(rg.w, q3));

        float s = nms_cls[idx];
        o_sig[idx] = 1.0f / (1.0f + expf(-s));

        float l[CC];
        float m = -INFINITY;
        #pragma unroll
        for (int c = 0; c < CC; c++) {
            l[c] = rcnn_cls[(size_t)idx * CC + c];
            m = fmaxf(m, l[c]);
        }
        float p[CC];
        float sum = 0.0f;
        #pragma unroll
        for (int c = 0; c < CC; c++) {
            p[c] = expf(l[c] - m);
            sum += p[c];
        }
        float inv = __fdiv_rn(1.0f, sum);
        int   am   = 0;
        float best = -INFINITY;
        #pragma unroll
        for (int c = 0; c < CC; c++) {
            p[c] = __fmul_rn(p[c], inv);
            o_probs[(size_t)idx * CC + c] = p[c];
            if (p[c] > best) { best = p[c]; am = c; }
        }
        // prep owns keep for amax==0 boxes (reference never keeps them)
        if (am == 0) o_keep[idx] = 0.0f;
        return;
    }

    // ------------------------- segmented gather -------------------------
    int g    = bid / NSEG;                 // group id
    int seg  = bid - g * NSEG;
    int b    = g / (CC - 1);
    int cls  = 1 + g % (CC - 1);
    int n0   = seg * SEGSZ;
    int n1   = n0 + SEGSZ;
    if (n1 > NN) n1 = NN;

    if (tid == 0) s_count = 0;
    __syncthreads();

    for (int n = n0 + tid; n < n1; n += THREADS) {
        const float* lg = rcnn_cls + ((size_t)b * NN + n) * CC;
        float l[CC];
        float bestl = -INFINITY, second = -INFINITY;
        int am = 0;
        #pragma unroll
        for (int c = 0; c < CC; c++) {
            float v = lg[c];
            l[c] = v;
            if (v > bestl) { second = bestl; bestl = v; am = c; }
            else if (v > second) second = v;
        }
        bool cand;
        float score = 0.0f;
        if (bestl - second > 1e-5f) {
            // unique max: argmax(probs) == argmax(logits)
            cand = (am == cls);
            if (cand) {
                float sum = 0.0f;
                #pragma unroll
                for (int c = 0; c < CC; c++) sum += expf(l[c] - bestl);
                float inv = __fdiv_rn(1.0f, sum);
                score = __fmul_rn(expf(l[cls] - bestl), inv);
            }
        } else {
            // near-tie: exact reference p sequence + first-max argmax
            float sum = 0.0f;
            #pragma unroll
            for (int c = 0; c < CC; c++) sum += expf(l[c] - bestl);
            float inv = __fdiv_rn(1.0f, sum);
            int amp = 0; float bp = -INFINITY; float sc = 0.0f;
            #pragma unroll
            for (int c = 0; c < CC; c++) {
                float p = __fmul_rn(expf(l[c] - bestl), inv);
                if (p > bp) { bp = p; amp = c; }
                if (c == cls) sc = p;
            }
            cand = (amp == cls);
            score = sc;
        }
        if (cand) {
            int pos = atomicAdd(&s_count, 1);   // shared atomic; order fixed by rank sort
            unsigned int sb = __float_as_uint(score);
            g_seglist[(size_t)bid * SEGCAP + pos] =
                ((unsigned long long)sb << 32)
              | (unsigned long long)(0xFFFFFFFFu - (unsigned)n);
        }
    }
    __syncthreads();
    if (tid == 0) g_segcnt[bid] = s_count;
}

// ===========================================================================
// Kernel 2: per-group NMS (80 blocks)
// ===========================================================================
// nmsbuf overlays:
//   fast:     maskb u32 [0,12800) | tlbr f4 [12800,17920) | area f [17920,19200)
//             sidx i32 [19200,20480) | keptw u32 [20480,20520)
//   fallback: keys u64 [0,32768) | st u8 [32768,35840)
__global__ void __launch_bounds__(THREADS)
k2_nms(const float* __restrict__ nms_reg,
       const float* __restrict__ rcnn_reg,
       const float* __restrict__ rcnn_cls,
       const unsigned int* __restrict__ red_raw,
       float* __restrict__ out)
{
    __shared__ unsigned char      nmsbuf[36864];
    __shared__ unsigned long long keysbuf[MAXM];
    __shared__ int scnt[NSEG];
    __shared__ int s_count;

    int tid  = threadIdx.x;
    int lane = tid & 31;
    int g    = blockIdx.x;
    int b    = g / (CC - 1);
    int cls  = 1 + g % (CC - 1);

    unsigned int wr = red_raw[0];
    float red = (wr < 0x10000u) ? (float)wr : __uint_as_float(wr);

    float* o_keep = out + BN * 9 + BN * CC;

    if (tid < NSEG) scnt[tid] = g_segcnt[g * NSEG + tid];
    __syncthreads();

    int off[NSEG];
    int M = 0;
    #pragma unroll
    for (int s = 0; s < NSEG; s++) { off[s] = M; M += scnt[s]; }

    if (M == 0) return;

    if (M <= MAXM) {
        // concat segment lists into shared keys
        #pragma unroll
        for (int s = 0; s < NSEG; s++) {
            int c = scnt[s];
            const unsigned long long* src = g_seglist + (size_t)(g * NSEG + s) * SEGCAP;
            for (int i = tid; i < c; i += THREADS) keysbuf[off[s] + i] = src[i];
        }
        __syncthreads();

        unsigned int* maskb = (unsigned int*)nmsbuf;
        float4*       tlbr  = (float4*)(nmsbuf + 12800);
        float*        area  = (float*)(nmsbuf + 17920);
        int*          sidx  = (int*)(nmsbuf + 19200);
        unsigned int* keptw = (unsigned int*)(nmsbuf + 20480);
        const int W = (M + 31) >> 5;

        // rank sort (keys unique -> deterministic descending order)
        unsigned long long myk[2]; int myrank[2]; int nown = 0;
        for (int i = tid; i < M; i += THREADS) {
            unsigned long long k = keysbuf[i];
            int r = 0;
            for (int j = 0; j < M; j++) r += (keysbuf[j] > k);
            myk[nown] = k; myrank[nown] = r; nown++;
        }
        __syncthreads();
        for (int q = 0; q < nown; q++) keysbuf[myrank[q]] = myk[q];
        __syncthreads();

        // stage sorted boxes (bit-exact recompute) + areas + indices
        for (int i = tid; i < M; i += THREADS) {
            int n = (int)(0xFFFFFFFFu - (unsigned)(keysbuf[i] & 0xFFFFFFFFu));
            sidx[i] = n;
            float4 v;
            load_box(nms_reg, rcnn_reg, red, b * NN + n, &v);
            tlbr[i] = v;
            area[i] = __fmul_rn(fmaxf(__fsub_rn(v.z, v.x), 0.0f),
                                fmaxf(__fsub_rn(v.w, v.y), 0.0f));
        }
        __syncthreads();

        // suppression matrix: thread owns (row i, word w); no atomics
        int ncells = M * W;
        for (int t = tid; t < ncells; t += THREADS) {
            int i = t / W;
            int w = t - i * W;
            int jbase = w << 5;
            unsigned int word = 0;
            if (jbase + 31 > i) {
                float4 bi = tlbr[i];
                float  ai = area[i];
                #pragma unroll 4
                for (int bit = 0; bit < 32; bit++) {
                    int j = jbase + bit;
                    if (j > i && j < M) {
                        float4 bj = tlbr[j];
                        float ih = fmaxf(__fsub_rn(fminf(bi.z, bj.z), fmaxf(bi.x, bj.x)), 0.0f);
                        float iw = fmaxf(__fsub_rn(fminf(bi.w, bj.w), fmaxf(bi.y, bj.y)), 0.0f);
                        float inter = __fmul_rn(ih, iw);
                        float uni   = __fsub_rn(__fadd_rn(ai, area[j]), inter);
                        float iou   = __fdiv_rn(inter, fmaxf(uni, 1e-9f));
                        if (iou > 0.5f) word |= (1u << bit);
                    }
                }
            }
            maskb[i * W + w] = word;
        }
        __syncthreads();

        // warp 0: branchless chunked greedy scan
        if (tid < 32) {
            unsigned int R = 0u, K = 0u;
            int ldslane = (lane < W) ? lane : (W - 1);
            unsigned int lanemask = (lane < W) ? 0xFFFFFFFFu : 0u;
            for (int c = 0; c < W; c++) {
                unsigned int curw = __shfl_sync(0xFFFFFFFFu, R, c);
                int ibase = c << 5;
                #pragma unroll 8
                for (int bit = 0; bit < 32; bit++) {
                    int i = ibase + bit;
                    unsigned int valid = (i < M) ? 0xFFFFFFFFu : 0u;
                    unsigned int keptm = (~(curw >> bit) & 1u) ? valid : 0u;
                    unsigned int mwc = maskb[i * W + c]       & valid;
                    unsigned int mwl = maskb[i * W + ldslane] & lanemask & valid;
                    curw |= (mwc & keptm);
                    R    |= (mwl & keptm);
                    K    |= ((lane == c) ? (keptm & (1u << bit)) : 0u);
                }
            }
            if (lane < W) keptw[lane] = K;
        }
        __syncthreads();

        // keep (0/1); in-batch index 0 never kept (reference scan quirk)
        for (int i = tid; i < M; i += THREADS) {
            int n = sidx[i];
            bool kept = (keptw[i >> 5] >> (i & 31)) & 1u;
            o_keep[b * NN + n] = (kept && n != 0) ? 1.0f : 0.0f;
        }
    } else {
        // -------- fallback (M > 320; statistically unreachable) --------
        unsigned long long* keys = (unsigned long long*)nmsbuf;   // cap 4096
        unsigned char*      st   = nmsbuf + 32768;                // cap 3000+
        if (tid == 0) s_count = 0;
        __syncthreads();
        // exact re-gather, direct reads
        for (int n = tid; n < NN; n += THREADS) {
            const float* lg = rcnn_cls + ((size_t)b * NN + n) * CC;
            float l[CC];
            float bestl = -INFINITY;
            #pragma unroll
            for (int c = 0; c < CC; c++) { l[c] = lg[c]; bestl = fmaxf(bestl, l[c]); }
            float sum = 0.0f;
            #pragma unroll
            for (int c = 0; c < CC; c++) sum += expf(l[c] - bestl);
            float inv = __fdiv_rn(1.0f, sum);
            int amp = 0; float bp = -INFINITY; float sc = 0.0f;
            #pragma unroll
            for (int c = 0; c < CC; c++) {
                float p = __fmul_rn(expf(l[c] - bestl), inv);
                if (p > bp) { bp = p; amp = c; }
                if (c == cls) sc = p;
            }
            if (amp == cls) {
                int pos = atomicAdd(&s_count, 1);
                unsigned int sb = __float_as_uint(sc);
                keys[pos] = ((unsigned long long)sb << 32)
                          | (unsigned long long)(0xFFFFFFFFu - (unsigned)n);
            }
        }
        __syncthreads();
        M = s_count;

        int P = 1;
        while (P < M) P <<= 1;
        for (int i = M + tid; i < P; i += THREADS) keys[i] = 0ULL;
        __syncthreads();
        for (int k = 2; k <= P; k <<= 1) {
            for (int j = k >> 1; j > 0; j >>= 1) {
                for (int i = tid; i < P; i += THREADS) {
                    int ixj = i ^ j;
                    if (ixj > i) {
                        unsigned long long a = keys[i];
                        unsigned long long c = keys[ixj];
                        bool dirDesc = ((i & k) == 0);
                        if ((a < c) == dirDesc) { keys[i] = c; keys[ixj] = a; }
                    }
                }
                __syncthreads();
            }
        }
        for (int i = tid; i < M; i += THREADS) st[i] = 0;   // 0=alive 1=supp 2=kept
        __syncthreads();
        for (int i = 0; i < M; i++) {
            if (st[i] == 0) {
                int ni = (int)(0xFFFFFFFFu - (unsigned)(keys[i] & 0xFFFFFFFFu));
                float4 vi; load_box(nms_reg, rcnn_reg, red, b * NN + ni, &vi);
                float ai = __fmul_rn(fmaxf(__fsub_rn(vi.z, vi.x), 0.0f),
                                     fmaxf(__fsub_rn(vi.w, vi.y), 0.0f));
                if (tid == 0) st[i] = 2;
                for (int j = i + 1 + tid; j < M; j += THREADS) {
                    if (st[j]) continue;
                    int nj = (int)(0xFFFFFFFFu - (unsigned)(keys[j] & 0xFFFFFFFFu));
                    float4 vj; load_box(nms_reg, rcnn_reg, red, b * NN + nj, &vj);
                    float aj = __fmul_rn(fmaxf(__fsub_rn(vj.z, vj.x), 0.0f),
                                         fmaxf(__fsub_rn(vj.w, vj.y), 0.0f));
                    float ih = fmaxf(__fsub_rn(fminf(vi.z, vj.z), fmaxf(vi.x, vj.x)), 0.0f);
                    float iw = fmaxf(__fsub_rn(fminf(vi.w, vj.w), fmaxf(vi.y, vj.y)), 0.0f);
                    float inter = __fmul_rn(ih, iw);
                    float uni   = __fsub_rn(__fadd_rn(ai, aj), inter);
                    float iou   = __fdiv_rn(inter, fmaxf(uni, 1e-9f));
                    if (iou > 0.5f) st[j] = 1;
                }
            }
            __syncthreads();
        }
        for (int i = tid; i < M; i += THREADS) {
            int n = (int)(0xFFFFFFFFu - (unsigned)(keys[i] & 0xFFFFFFFFu));
            o_keep[b * NN + n] = (st[i] == 2 && n != 0) ? 1.0f : 0.0f;
        }
    }
}

extern "C" void kernel_launch(void* const* d_in, const int* in_sizes, int n_in,
                              void* d_out, int out_size)
{
    const float* nms_reg  = (const float*)d_in[0];
    const float* nms_cls  = (const float*)d_in[1];
    const float* rcnn_reg = (const float*)d_in[2];
    const float* rcnn_cls = (const float*)d_in[3];
    const unsigned int* red = (const unsigned int*)d_in[4];
    float* out = (float*)d_out;

    k1_prep_gather<<<NBLK1, THREADS>>>(nms_reg, nms_cls, rcnn_reg, rcnn_cls, red, out);
    k2_nms<<<NGROUPS, THREADS>>>(nms_reg, rcnn_reg, rcnn_cls, red, out);
}

// round 14
// speedup vs baseline: 1.6489x; 1.4213x over previous
#include <cuda_runtime.h>
#include <math.h>

#define BB 4
#define NN 3000
#define CC 21
#define BN (BB*NN)

#define NGROUPS (BB*(CC-1))       // 80
#define THREADS 512
#define PREP_BLOCKS ((BN + THREADS - 1) / THREADS)   // 24
#define NBLK (NGROUPS + PREP_BLOCKS)                 // 104
#define MAXM  320
#define WMAX  10
#define FCAP  504

// out layout (float32): [rounded BN*4][sigmoid BN][boxes BN*4][probs BN*C][keep BN]

// sbuf overlay (group path):
//   keys u64 [0,4096) | tlbr f4 [4096,9216) | area f [9216,10496) | sidx i32 [10496,11776)
//   keptw u32 [11776,11816)
//   fallback: keys u64 [0,32768)
__shared__ unsigned char sbuf[32768];
__shared__ unsigned int  maskbuf[MAXM * WMAX];
__shared__ int           candbuf[FCAP];
__shared__ int s_count, s_filt;

// exact reference-sequence softmax score for class `cls` given 21 logits.
__device__ __forceinline__ float softmax_score(const float* l, float m, int cls)
{
    float sum = 0.0f;
    #pragma unroll
    for (int c = 0; c < CC; c++) sum += expf(l[c] - m);
    float inv = __fdiv_rn(1.0f, sum);
    return __fmul_rn(expf(l[cls] - m), inv);
}

__device__ __forceinline__ void load_box(const float* __restrict__ nms_reg,
                                         const float* __restrict__ rcnn_reg,
                                         float red, int gidx, float4* box)
{
    float4 r  = ((const float4*)nms_reg)[gidx];
    float4 rg = ((const float4*)rcnn_reg)[gidx];
    float q0 = __fdiv_rn(floorf(__fmul_rn(r.x, red)), red);
    float q1 = __fdiv_rn(floorf(__fmul_rn(r.y, red)), red);
    float q2 = __fdiv_rn(ceilf(__fmul_rn(r.z, red)), red);
    float q3 = __fdiv_rn(ceilf(__fmul_rn(r.w, red)), red);
    box->x = __fadd_rn(rg.x, q0);
    box->y = __fadd_rn(rg.y, q1);
    box->z = __fadd_rn(rg.z, q2);
    box->w = __fadd_rn(rg.w, q3);
}

__global__ void __launch_bounds__(THREADS)
fused_kernel(const float* __restrict__ nms_reg,
             const float* __restrict__ nms_cls,
             const float* __restrict__ rcnn_reg,
             const float* __restrict__ rcnn_cls,
             const unsigned int* __restrict__ red_raw,
             float* __restrict__ out)
{
    int tid  = threadIdx.x;
    int lane = tid & 31;
    int bid  = blockIdx.x;

    unsigned int wr = red_raw[0];
    float red = (wr < 0x10000u) ? (float)wr : __uint_as_float(wr);

    float* o_keep = out + BN * 9 + BN * CC;

    if (bid >= NGROUPS) {
        // ------------------------- prep path (R6-verbatim) -------------------
        int idx = (bid - NGROUPS) * THREADS + tid;
        if (idx >= BN) return;

        float* o_round = out;
        float* o_sig   = out + BN * 4;
        float* o_boxes = out + BN * 5;
        float* o_probs = out + BN * 9;

        float4 r = ((const float4*)nms_reg)[idx];
        float q0 = __fdiv_rn(floorf(__fmul_rn(r.x, red)), red);
        float q1 = __fdiv_rn(floorf(__fmul_rn(r.y, red)), red);
        float q2 = __fdiv_rn(ceilf(__fmul_rn(r.z, red)), red);
        float q3 = __fdiv_rn(ceilf(__fmul_rn(r.w, red)), red);
        ((float4*)o_round)[idx] = make_float4(q0, q1, q2, q3);

        float4 rg = ((const float4*)rcnn_reg)[idx];
        ((float4*)o_boxes)[idx] = make_float4(
            __fadd_rn(rg.x, q0), __fadd_rn(rg.y, q1),
            __fadd_rn(rg.z, q2), __fadd_rn(rg.w, q3));

        float s = nms_cls[idx];
        o_sig[idx] = 1.0f / (1.0f + expf(-s));

        float l[CC];
        float m = -INFINITY;
        #pragma unroll
        for (int c = 0; c < CC; c++) {
            l[c] = rcnn_cls[(size_t)idx * CC + c];
            m = fmaxf(m, l[c]);
        }
        float p[CC];
        float sum = 0.0f;
        #pragma unroll
        for (int c = 0; c < CC; c++) {
            p[c] = expf(l[c] - m);
            sum += p[c];
        }
        float inv = __fdiv_rn(1.0f, sum);
        int   am   = 0;
        float best = -INFINITY;
        #pragma unroll
        for (int c = 0; c < CC; c++) {
            p[c] = __fmul_rn(p[c], inv);
            o_probs[(size_t)idx * CC + c] = p[c];
            if (p[c] > best) { best = p[c]; am = c; }
        }
        if (am == 0) o_keep[idx] = 0.0f;   // amax==0 boxes are never kept
        return;
    }

    // ------------------------- group path -------------------------
    int b   = bid / (CC - 1);
    int cls = 1 + bid % (CC - 1);

    unsigned long long* keys = (unsigned long long*)sbuf;

    if (tid == 0) { s_count = 0; s_filt = 0; }
    __syncthreads();

    // --- pass 1: register-lean superset filter (tree max, no arrays) ---
    for (int n = tid; n < NN; n += THREADS) {
        const float* lg = rcnn_cls + ((size_t)b * NN + n) * CC;
        float a0  = fmaxf(lg[0],  lg[1]);
        float a1  = fmaxf(lg[2],  lg[3]);
        float a2  = fmaxf(lg[4],  lg[5]);
        float a3  = fmaxf(lg[6],  lg[7]);
        float a4  = fmaxf(lg[8],  lg[9]);
        float a5  = fmaxf(lg[10], lg[11]);
        float a6  = fmaxf(lg[12], lg[13]);
        float a7  = fmaxf(lg[14], lg[15]);
        float a8  = fmaxf(lg[16], lg[17]);
        float a9  = fmaxf(lg[18], lg[19]);
        float a10 = lg[20];
        a0 = fmaxf(a0, a1);  a2 = fmaxf(a2, a3);
        a4 = fmaxf(a4, a5);  a6 = fmaxf(a6, a7);
        a8 = fmaxf(a8, a9);
        a0 = fmaxf(a0, a2);  a4 = fmaxf(a4, a6);
        a8 = fmaxf(a8, a10);
        float mx = fmaxf(fmaxf(a0, a4), a8);
        float vc = lg[cls];
        if (vc >= mx - 1e-5f) {
            int pos = atomicAdd(&s_filt, 1);
            if (pos < FCAP) candbuf[pos] = n;
        }
    }
    __syncthreads();
    int F = s_filt;

    if (F <= FCAP) {
        // --- pass 2: exact R6 candidate test, dense over compacted list ---
        for (int q = tid; q < F; q += THREADS) {
            int n = candbuf[q];
            const float* lg = rcnn_cls + ((size_t)b * NN + n) * CC;
            float l[CC];
            float bestl = -INFINITY, second = -INFINITY;
            int am = 0;
            #pragma unroll
            for (int c = 0; c < CC; c++) {
                float v = lg[c];
                l[c] = v;
                if (v > bestl) { second = bestl; bestl = v; am = c; }
                else if (v > second) second = v;
            }
            bool cand;
            float score = 0.0f;
            if (bestl - second > 1e-5f) {
                // unique max: argmax(probs) == argmax(logits)
                cand = (am == cls);
                if (cand) score = softmax_score(l, bestl, cls);
            } else {
                // near-tie: exact reference p computation + first-max argmax
                float sum = 0.0f;
                float p[CC];
                #pragma unroll
                for (int c = 0; c < CC; c++) { p[c] = expf(l[c] - bestl); sum += p[c]; }
                float inv = __fdiv_rn(1.0f, sum);
                int amp = 0; float bp = -INFINITY;
                #pragma unroll
                for (int c = 0; c < CC; c++) {
                    p[c] = __fmul_rn(p[c], inv);
                    if (p[c] > bp) { bp = p[c]; amp = c; }
                }
                cand = (amp == cls);
                score = p[cls];
            }
            if (cand) {
                int pos = atomicAdd(&s_count, 1);
                if (pos < MAXM) {
                    unsigned int sb = __float_as_uint(score);
                    keys[pos] = ((unsigned long long)sb << 32)
                              | (unsigned long long)(0xFFFFFFFFu - (unsigned)n);
                }
            }
        }
    } else {
        // filter overflow (unreachable for this data): full exact scan (R6)
        for (int n = tid; n < NN; n += THREADS) {
            const float* lg = rcnn_cls + ((size_t)b * NN + n) * CC;
            float l[CC];
            float bestl = -INFINITY, second = -INFINITY;
            int am = 0;
            #pragma unroll
            for (int c = 0; c < CC; c++) {
                float v = lg[c];
                l[c] = v;
                if (v > bestl) { second = bestl; bestl = v; am = c; }
                else if (v > second) second = v;
            }
            bool cand;
            float score = 0.0f;
            if (bestl - second > 1e-5f) {
                cand = (am == cls);
                if (cand) score = softmax_score(l, bestl, cls);
            } else {
                float sum = 0.0f;
                float p[CC];
                #pragma unroll
                for (int c = 0; c < CC; c++) { p[c] = expf(l[c] - bestl); sum += p[c]; }
                float inv = __fdiv_rn(1.0f, sum);
                int amp = 0; float bp = -INFINITY;
                #pragma unroll
                for (int c = 0; c < CC; c++) {
                    p[c] = __fmul_rn(p[c], inv);
                    if (p[c] > bp) { bp = p[c]; amp = c; }
                }
                cand = (amp == cls);
                score = p[cls];
            }
            if (cand) {
                int pos = atomicAdd(&s_count, 1);
                if (pos < MAXM) {
                    unsigned int sb = __float_as_uint(score);
                    keys[pos] = ((unsigned long long)sb << 32)
                              | (unsigned long long)(0xFFFFFFFFu - (unsigned)n);
                }
            }
        }
    }
    __syncthreads();
    int M = s_count;
    if (M == 0) return;

    if (M <= MAXM) {
        float4*       tlbr  = (float4*)(sbuf + 4096);
        float*        area  = (float*)(sbuf + 9216);
        int*          sidx  = (int*)(sbuf + 10496);
        unsigned int* keptw = (unsigned int*)(sbuf + 11776);
        const int W = (M + 31) >> 5;

        // rank sort (keys unique -> deterministic descending order)
        unsigned long long myk; int myrank = -1;
        if (tid < M) {
            myk = keys[tid];
            int r = 0;
            for (int j = 0; j < M; j++) r += (keys[j] > myk);
            myrank = r;
        }
        __syncthreads();
        if (myrank >= 0) keys[myrank] = myk;
        __syncthreads();

        // stage sorted boxes (bit-exact recompute) + areas + indices
        if (tid < M) {
            int n = (int)(0xFFFFFFFFu - (unsigned)(keys[tid] & 0xFFFFFFFFu));
            sidx[tid] = n;
            float4 v;
            load_box(nms_reg, rcnn_reg, red, b * NN + n, &v);
            tlbr[tid] = v;
            area[tid] = __fmul_rn(fmaxf(__fsub_rn(v.z, v.x), 0.0f),
                                  fmaxf(__fsub_rn(v.w, v.y), 0.0f));
        }
        __syncthreads();

        // suppression matrix: thread owns (row i, word w); no atomics
        int ncells = M * W;
        for (int t = tid; t < ncells; t += THREADS) {
            int i = t / W;
            int w = t - i * W;
            int jbase = w << 5;
            unsigned int word = 0;
            if (jbase + 31 > i) {
                float4 bi = tlbr[i];
                float  ai = area[i];
                #pragma unroll 4
                for (int bit = 0; bit < 32; bit++) {
                    int j = jbase + bit;
                    if (j > i && j < M) {
                        float4 bj = tlbr[j];
                        float ih = fmaxf(__fsub_rn(fminf(bi.z, bj.z), fmaxf(bi.x, bj.x)), 0.0f);
                        float iw = fmaxf(__fsub_rn(fminf(bi.w, bj.w), fmaxf(bi.y, bj.y)), 0.0f);
                        float inter = __fmul_rn(ih, iw);
                        float uni   = __fsub_rn(__fadd_rn(ai, area[j]), inter);
                        float iou   = __fdiv_rn(inter, fmaxf(uni, 1e-9f));
                        if (iou > 0.5f) word |= (1u << bit);
                    }
                }
            }
            maskbuf[i * W + w] = word;
        }
        __syncthreads();

        // warp 0: branchless chunked greedy scan
        if (tid < 32) {
            unsigned int R = 0u, K = 0u;
            int ldslane = (lane < W) ? lane : (W - 1);
            unsigned int lanemask = (lane < W) ? 0xFFFFFFFFu : 0u;
            for (int c = 0; c < W; c++) {
                unsigned int curw = __shfl_sync(0xFFFFFFFFu, R, c);
                int ibase = c << 5;
                #pragma unroll 8
                for (int bit = 0; bit < 32; bit++) {
                    int i = ibase + bit;
                    unsigned int valid = (i < M) ? 0xFFFFFFFFu : 0u;
                    unsigned int keptm = (~(curw >> bit) & 1u) ? valid : 0u;
                    unsigned int mwc = maskbuf[i * W + c]       & valid;
                    unsigned int mwl = maskbuf[i * W + ldslane] & lanemask & valid;
                    curw |= (mwc & keptm);
                    R    |= (mwl & keptm);
                    K    |= ((lane == c) ? (keptm & (1u << bit)) : 0u);
                }
            }
            if (lane < W) keptw[lane] = K;
        }
        __syncthreads();

        // keep (0/1); in-batch index 0 never kept (reference scan quirk)
        if (tid < M) {
            int n = sidx[tid];
            bool kept = (keptw[tid >> 5] >> (tid & 31)) & 1u;
            o_keep[b * NN + n] = (kept && n != 0) ? 1.0f : 0.0f;
        }
    } else {
        // -------- fallback (M > 320; statistically unreachable) --------
        int P = 1;
        while (P < M) P <<= 1;
        for (int i = M + tid; i < P; i += THREADS) keys[i] = 0ULL;
        __syncthreads();
        for (int k = 2; k <= P; k <<= 1) {
            for (int j = k >> 1; j > 0; j >>= 1) {
                for (int i = tid; i < P; i += THREADS) {
                    int ixj = i ^ j;
                    if (ixj > i) {
                        unsigned long long a = keys[i];
                        unsigned long long c = keys[ixj];
                        bool dirDesc = ((i & k) == 0);
                        if ((a < c) == dirDesc) { keys[i] = c; keys[ixj] = a; }
                    }
                }
                __syncthreads();
            }
        }
        unsigned char* st = (unsigned char*)maskbuf;   // 0=alive 1=supp 2=kept
        for (int i = tid; i < M; i += THREADS) st[i] = 0;
        __syncthreads();
        for (int i = 0; i < M; i++) {
            if (st[i] == 0) {
                int ni = (int)(0xFFFFFFFFu - (unsigned)(keys[i] & 0xFFFFFFFFu));
                float4 vi; load_box(nms_reg, rcnn_reg, red, b * NN + ni, &vi);
                float ai = __fmul_rn(fmaxf(__fsub_rn(vi.z, vi.x), 0.0f),
                                     fmaxf(__fsub_rn(vi.w, vi.y), 0.0f));
                if (tid == 0) st[i] = 2;
                for (int j = i + 1 + tid; j < M; j += THREADS) {
                    if (st[j]) continue;
                    int nj = (int)(0xFFFFFFFFu - (unsigned)(keys[j] & 0xFFFFFFFFu));
                    float4 vj; load_box(nms_reg, rcnn_reg, red, b * NN + nj, &vj);
                    float aj = __fmul_rn(fmaxf(__fsub_rn(vj.z, vj.x), 0.0f),
                                         fmaxf(__fsub_rn(vj.w, vj.y), 0.0f));
                    float ih = fmaxf(__fsub_rn(fminf(vi.z, vj.z), fmaxf(vi.x, vj.x)), 0.0f);
                    float iw = fmaxf(__fsub_rn(fminf(vi.w, vj.w), fmaxf(vi.y, vj.y)), 0.0f);
                    float inter = __fmul_rn(ih, iw);
                    float uni   = __fsub_rn(__fadd_rn(ai, aj), inter);
                    float iou   = __fdiv_rn(inter, fmaxf(uni, 1e-9f));
                    if (iou > 0.5f) st[j] = 1;
                }
            }
            __syncthreads();
        }
        for (int i = tid; i < M; i += THREADS) {
            int n = (int)(0xFFFFFFFFu - (unsigned)(keys[i] & 0xFFFFFFFFu));
            o_keep[b * NN + n] = (st[i] == 2 && n != 0) ? 1.0f : 0.0f;
        }
    }
}

extern "C" void kernel_launch(void* const* d_in, const int* in_sizes, int n_in,
                              void* d_out, int out_size)
{
    const float* nms_reg  = (const float*)d_in[0];
    const float* nms_cls  = (const float*)d_in[1];
    const float* rcnn_reg = (const float*)d_in[2];
    const float* rcnn_cls = (const float*)d_in[3];
    const unsigned int* red = (const unsigned int*)d_in[4];
    float* out = (float*)d_out;

    fused_kernel<<<NBLK, THREADS>>>(nms_reg, nms_cls, rcnn_reg, rcnn_cls, red, out);
}

// round 15
// speedup vs baseline: 1.9835x; 1.2029x over previous
#include <cuda_runtime.h>
#include <math.h>

#define BB 4
#define NN 3000
#define CC 21
#define BN (BB*NN)

#define NGROUPS (BB*(CC-1))       // 80
#define THREADS 512
#define PREP_PER_BLK 256
#define PREP_BLOCKS ((BN + PREP_PER_BLK - 1) / PREP_PER_BLK)   // 48
#define NBLK (NGROUPS + PREP_BLOCKS)                           // 128
#define MAXM  320
#define WMAX  10

// out layout (float32): [rounded BN*4][sigmoid BN][boxes BN*4][probs BN*C][keep BN]

// sbuf overlay (group path):
//   keys u64 [0,4096) | tlbr f4 [4096,9216) | area f [9216,10496) | sidx i32 [10496,11776)
//   keptw u32 [11776,11816)
//   fallback: keys u64 [0,32768)
__shared__ unsigned char sbuf[32768];
__shared__ unsigned int  maskbuf[MAXM * WMAX];
__shared__ int s_count;

// exact reference-sequence softmax score for class `cls` given 21 logits.
__device__ __forceinline__ float softmax_score(const float* l, float m, int cls)
{
    float sum = 0.0f;
    #pragma unroll
    for (int c = 0; c < CC; c++) sum += expf(l[c] - m);
    float inv = __fdiv_rn(1.0f, sum);
    return __fmul_rn(expf(l[cls] - m), inv);
}

__device__ __forceinline__ void load_box(const float* __restrict__ nms_reg,
                                         const float* __restrict__ rcnn_reg,
                                         float red, int gidx, float4* box)
{
    float4 r  = ((const float4*)nms_reg)[gidx];
    float4 rg = ((const float4*)rcnn_reg)[gidx];
    float q0 = __fdiv_rn(floorf(__fmul_rn(r.x, red)), red);
    float q1 = __fdiv_rn(floorf(__fmul_rn(r.y, red)), red);
    float q2 = __fdiv_rn(ceilf(__fmul_rn(r.z, red)), red);
    float q3 = __fdiv_rn(ceilf(__fmul_rn(r.w, red)), red);
    box->x = __fadd_rn(rg.x, q0);
    box->y = __fadd_rn(rg.y, q1);
    box->z = __fadd_rn(rg.z, q2);
    box->w = __fadd_rn(rg.w, q3);
}

// bit-exact replica of (__fdiv_rn(inter, d) > 0.5f) with ~zero MUFU use.
// 2*inter is exact; q <= 0.5 => fl(q) <= 0.5, so the false side needs no
// tolerance. Only the sliver d < 2*inter < d*(1+1e-6) needs the real divide.
__device__ __forceinline__ bool iou_gt_half(float inter, float d)
{
    float t2 = 2.0f * inter;
    if (!(t2 > d)) return false;
    if (t2 < __fmul_rn(d, 1.000001f))
        return __fdiv_rn(inter, d) > 0.5f;
    return true;
}

__global__ void __launch_bounds__(THREADS)
fused_kernel(const float* __restrict__ nms_reg,
             const float* __restrict__ nms_cls,
             const float* __restrict__ rcnn_reg,
             const float* __restrict__ rcnn_cls,
             const unsigned int* __restrict__ red_raw,
             float* __restrict__ out)
{
    int tid  = threadIdx.x;
    int lane = tid & 31;
    int bid  = blockIdx.x;

    unsigned int wr = red_raw[0];
    float red = (wr < 0x10000u) ? (float)wr : __uint_as_float(wr);

    float* o_keep = out + BN * 9 + BN * CC;

    if (bid >= NGROUPS) {
        // ---------------- prep path (256 boxes/block -> MUFU spread) --------
        if (tid >= PREP_PER_BLK) return;
        int idx = (bid - NGROUPS) * PREP_PER_BLK + tid;
        if (idx >= BN) return;

        float* o_round = out;
        float* o_sig   = out + BN * 4;
        float* o_boxes = out + BN * 5;
        float* o_probs = out + BN * 9;

        float4 r = ((const float4*)nms_reg)[idx];
        float q0 = __fdiv_rn(floorf(__fmul_rn(r.x, red)), red);
        float q1 = __fdiv_rn(floorf(__fmul_rn(r.y, red)), red);
        float q2 = __fdiv_rn(ceilf(__fmul_rn(r.z, red)), red);
        float q3 = __fdiv_rn(ceilf(__fmul_rn(r.w, red)), red);
        ((float4*)o_round)[idx] = make_float4(q0, q1, q2, q3);

        float4 rg = ((const float4*)rcnn_reg)[idx];
        ((float4*)o_boxes)[idx] = make_float4(
            __fadd_rn(rg.x, q0), __fadd_rn(rg.y, q1),
            __fadd_rn(rg.z, q2), __fadd_rn(rg.w, q3));

        float s = nms_cls[idx];
        o_sig[idx] = 1.0f / (1.0f + expf(-s));

        float l[CC];
        float m = -INFINITY;
        #pragma unroll
        for (int c = 0; c < CC; c++) {
            l[c] = rcnn_cls[(size_t)idx * CC + c];
            m = fmaxf(m, l[c]);
        }
        float p[CC];
        float sum = 0.0f;
        #pragma unroll
        for (int c = 0; c < CC; c++) {
            p[c] = expf(l[c] - m);
            sum += p[c];
        }
        float inv = __fdiv_rn(1.0f, sum);
        int   am   = 0;
        float best = -INFINITY;
        #pragma unroll
        for (int c = 0; c < CC; c++) {
            p[c] = __fmul_rn(p[c], inv);
            o_probs[(size_t)idx * CC + c] = p[c];
            if (p[c] > best) { best = p[c]; am = c; }
        }
        if (am == 0) o_keep[idx] = 0.0f;   // amax==0 boxes are never kept
        return;
    }

    // ------------------------- group path (R6 gather) -------------------------
    int b   = bid / (CC - 1);
    int cls = 1 + bid % (CC - 1);

    unsigned long long* keys = (unsigned long long*)sbuf;

    if (tid == 0) s_count = 0;
    __syncthreads();

    for (int n = tid; n < NN; n += THREADS) {
        const float* lg = rcnn_cls + ((size_t)b * NN + n) * CC;
        float l[CC];
        float bestl = -INFINITY, second = -INFINITY;
        int am = 0;
        #pragma unroll
        for (int c = 0; c < CC; c++) {
            float v = lg[c];
            l[c] = v;
            if (v > bestl) { second = bestl; bestl = v; am = c; }
            else if (v > second) second = v;
        }
        bool cand;
        float score = 0.0f;
        if (bestl - second > 1e-5f) {
            // unique max: argmax(probs) == argmax(logits)
            cand = (am == cls);
            if (cand) score = softmax_score(l, bestl, cls);
        } else {
            // near-tie: exact reference p computation + first-max argmax
            float sum = 0.0f;
            float p[CC];
            #pragma unroll
            for (int c = 0; c < CC; c++) { p[c] = expf(l[c] - bestl); sum += p[c]; }
            float inv = __fdiv_rn(1.0f, sum);
            int amp = 0; float bp = -INFINITY;
            #pragma unroll
            for (int c = 0; c < CC; c++) {
                p[c] = __fmul_rn(p[c], inv);
                if (p[c] > bp) { bp = p[c]; amp = c; }
            }
            cand = (amp == cls);
            score = p[cls];
        }
        if (cand) {
            int pos = atomicAdd(&s_count, 1);
            if (pos < MAXM) {
                unsigned int sb = __float_as_uint(score);
                keys[pos] = ((unsigned long long)sb << 32)
                          | (unsigned long long)(0xFFFFFFFFu - (unsigned)n);
            }
        }
    }
    __syncthreads();
    int M = s_count;
    if (M == 0) return;

    if (M <= MAXM) {
        float4*       tlbr  = (float4*)(sbuf + 4096);
        float*        area  = (float*)(sbuf + 9216);
        int*          sidx  = (int*)(sbuf + 10496);
        unsigned int* keptw = (unsigned int*)(sbuf + 11776);
        const int W = (M + 31) >> 5;

        // rank sort (keys unique -> deterministic descending order)
        unsigned long long myk; int myrank = -1;
        if (tid < M) {
            myk = keys[tid];
            int r = 0;
            for (int j = 0; j < M; j++) r += (keys[j] > myk);
            myrank = r;
        }
        __syncthreads();
        if (myrank >= 0) keys[myrank] = myk;
        __syncthreads();

        // stage sorted boxes (bit-exact recompute) + areas + indices
        if (tid < M) {
            int n = (int)(0xFFFFFFFFu - (unsigned)(keys[tid] & 0xFFFFFFFFu));
            sidx[tid] = n;
            float4 v;
            load_box(nms_reg, rcnn_reg, red, b * NN + n, &v);
            tlbr[tid] = v;
            area[tid] = __fmul_rn(fmaxf(__fsub_rn(v.z, v.x), 0.0f),
                                  fmaxf(__fsub_rn(v.w, v.y), 0.0f));
        }
        __syncthreads();

        // suppression matrix: thread owns (row i, word w); division-free IOU
        int ncells = M * W;
        for (int t = tid; t < ncells; t += THREADS) {
            int i = t / W;
            int w = t - i * W;
            int jbase = w << 5;
            unsigned int word = 0;
            if (jbase + 31 > i) {
                float4 bi = tlbr[i];
                float  ai = area[i];
                #pragma unroll 4
                for (int bit = 0; bit < 32; bit++) {
                    int j = jbase + bit;
                    if (j > i && j < M) {
                        float4 bj = tlbr[j];
                        float ih = fmaxf(__fsub_rn(fminf(bi.z, bj.z), fmaxf(bi.x, bj.x)), 0.0f);
                        float iw = fmaxf(__fsub_rn(fminf(bi.w, bj.w), fmaxf(bi.y, bj.y)), 0.0f);
                        float inter = __fmul_rn(ih, iw);
                        float uni   = __fsub_rn(__fadd_rn(ai, area[j]), inter);
                        float d     = fmaxf(uni, 1e-9f);
                        if (iou_gt_half(inter, d)) word |= (1u << bit);
                    }
                }
            }
            maskbuf[i * W + w] = word;
        }
        __syncthreads();

        // warp 0: branchless chunked greedy scan
        if (tid < 32) {
            unsigned int R = 0u, K = 0u;
            int ldslane = (lane < W) ? lane : (W - 1);
            unsigned int lanemask = (lane < W) ? 0xFFFFFFFFu : 0u;
            for (int c = 0; c < W; c++) {
                unsigned int curw = __shfl_sync(0xFFFFFFFFu, R, c);
                int ibase = c << 5;
                #pragma unroll 8
                for (int bit = 0; bit < 32; bit++) {
                    int i = ibase + bit;
                    unsigned int valid = (i < M) ? 0xFFFFFFFFu : 0u;
                    unsigned int keptm = (~(curw >> bit) & 1u) ? valid : 0u;
                    unsigned int mwc = maskbuf[i * W + c]       & valid;
                    unsigned int mwl = maskbuf[i * W + ldslane] & lanemask & valid;
                    curw |= (mwc & keptm);
                    R    |= (mwl & keptm);
                    K    |= ((lane == c) ? (keptm & (1u << bit)) : 0u);
                }
            }
            if (lane < W) keptw[lane] = K;
        }
        __syncthreads();

        // keep (0/1); in-batch index 0 never kept (reference scan quirk)
        if (tid < M) {
            int n = sidx[tid];
            bool kept = (keptw[tid >> 5] >> (tid & 31)) & 1u;
            o_keep[b * NN + n] = (kept && n != 0) ? 1.0f : 0.0f;
        }
    } else {
        // -------- fallback (M > 320; statistically unreachable) --------
        int P = 1;
        while (P < M) P <<= 1;
        for (int i = M + tid; i < P; i += THREADS) keys[i] = 0ULL;
        __syncthreads();
        for (int k = 2; k <= P; k <<= 1) {
            for (int j = k >> 1; j > 0; j >>= 1) {
                for (int i = tid; i < P; i += THREADS) {
                    int ixj = i ^ j;
                    if (ixj > i) {
                        unsigned long long a = keys[i];
                        unsigned long long c = keys[ixj];
                        bool dirDesc = ((i & k) == 0);
                        if ((a < c) == dirDesc) { keys[i] = c; keys[ixj] = a; }
                    }
                }
                __syncthreads();
            }
        }
        unsigned char* st = (unsigned char*)maskbuf;   // 0=alive 1=supp 2=kept
        for (int i = tid; i < M; i += THREADS) st[i] = 0;
        __syncthreads();
        for (int i = 0; i < M; i++) {
            if (st[i] == 0) {
                int ni = (int)(0xFFFFFFFFu - (unsigned)(keys[i] & 0xFFFFFFFFu));
                float4 vi; load_box(nms_reg, rcnn_reg, red, b * NN + ni, &vi);
                float ai = __fmul_rn(fmaxf(__fsub_rn(vi.z, vi.x), 0.0f),
                                     fmaxf(__fsub_rn(vi.w, vi.y), 0.0f));
                if (tid == 0) st[i] = 2;
                for (int j = i + 1 + tid; j < M; j += THREADS) {
                    if (st[j]) continue;
                    int nj = (int)(0xFFFFFFFFu - (unsigned)(keys[j] & 0xFFFFFFFFu));
                    float4 vj; load_box(nms_reg, rcnn_reg, red, b * NN + nj, &vj);
                    float aj = __fmul_rn(fmaxf(__fsub_rn(vj.z, vj.x), 0.0f),
                                         fmaxf(__fsub_rn(vj.w, vj.y), 0.0f));
                    float ih = fmaxf(__fsub_rn(fminf(vi.z, vj.z), fmaxf(vi.x, vj.x)), 0.0f);
                    float iw = fmaxf(__fsub_rn(fminf(vi.w, vj.w), fmaxf(vi.y, vj.y)), 0.0f);
                    float inter = __fmul_rn(ih, iw);
                    float uni   = __fsub_rn(__fadd_rn(ai, aj), inter);
                    float d     = fmaxf(uni, 1e-9f);
                    if (iou_gt_half(inter, d)) st[j] = 1;
                }
            }
            __syncthreads();
        }
        for (int i = tid; i < M; i += THREADS) {
            int n = (int)(0xFFFFFFFFu - (unsigned)(keys[i] & 0xFFFFFFFFu));
            o_keep[b * NN + n] = (st[i] == 2 && n != 0) ? 1.0f : 0.0f;
        }
    }
}

extern "C" void kernel_launch(void* const* d_in, const int* in_sizes, int n_in,
                              void* d_out, int out_size)
{
    const float* nms_reg  = (const float*)d_in[0];
    const float* nms_cls  = (const float*)d_in[1];
    const float* rcnn_reg = (const float*)d_in[2];
    const float* rcnn_cls = (const float*)d_in[3];
    const unsigned int* red = (const unsigned int*)d_in[4];
    float* out = (float*)d_out;

    fused_kernel<<<NBLK, THREADS>>>(nms_reg, nms_cls, rcnn_reg, rcnn_cls, red, out);
}